// round 3
// baseline (speedup 1.0000x reference)
#include <cuda_runtime.h>

// HSTU jagged causal attention, fp32 SIMT with packed f32x2 FMA.
//   out[i] = sum_{j<=i} silu(q_i . k_j / sqrt(D)) / max_seqlen * v_j   per (seq, head)
// Shapes (fixed by problem): H=8, D=DV=128, B=8, total tokens 5888, max_seqlen=1024.
//
// Design:
//  - CTA = (row-tile of 64, head, batch); 128 threads.
//  - smem: Qt[128][64], Kt[128][64] transposed + XOR-swizzled (conflict-free
//    vectorized reads for outer-product GEMM); Vs[64][128] with bit-permuted
//    column groups (2-phase LDS.128 reads); Ps (P^T, swizzled) aliases Kt.
//  - Score GEMM 64x64x128 and PV GEMM 64x128x64 both via fma.rn.f32x2
//    (2x over 3-reg FFMA on sm_103a, which issues at rt_SMSP=2).
//  - Reversed blockIdx.x: biggest causal tiles scheduled first.

#define HH   8
#define DD   128
#define DDV  128
#define HD   1024           // H * D
#define BM   64
#define BN   64
#define NTH  128
#define MAXTILES 16         // ceil(max_seqlen / BM) = 1024/64
#define ALPHA 0.08838834764831845f  // 1/sqrt(128)

// smem layout in floats. Ps aliases Kt (Kt is dead during epilogue/PV).
#define SM_Q 0
#define SM_K 8192
#define SM_P 8192
#define SM_V 16384
#define SMEM_FLOATS 24576   // 96 KB -> 2 CTAs / SM

typedef unsigned long long ull;

__device__ __forceinline__ ull dup2(float x) {
    ull r;
    asm("mov.b64 %0, {%1, %2};" : "=l"(r) : "f"(x), "f"(x));
    return r;
}
__device__ __forceinline__ ull ffma2(ull a, ull b, ull c) {
    ull d;
    asm("fma.rn.f32x2 %0, %1, %2, %3;" : "=l"(d) : "l"(a), "l"(b), "l"(c));
    return d;
}
__device__ __forceinline__ float2 unpk(ull a) {
    float2 r;
    asm("mov.b64 {%0, %1}, %2;" : "=f"(r.x), "=f"(r.y) : "l"(a));
    return r;
}

__global__ void __launch_bounds__(NTH)
hstu_attn_kernel(const float* __restrict__ tq,
                 const float* __restrict__ tk,
                 const float* __restrict__ tv,
                 const int*   __restrict__ offsets,
                 const int*   __restrict__ p_msl,
                 const int*   __restrict__ p_ssl,
                 float*       __restrict__ out)
{
    extern __shared__ float sm[];
    float* Qt = sm + SM_Q;   // [d:128][m:64] swizzled
    float* Kt = sm + SM_K;   // [d:128][n:64] swizzled
    float* Ps = sm + SM_P;   // [j:64][m:64] swizzled (aliases Kt)
    float* Vs = sm + SM_V;   // [j:64][dv:128] column-group permuted

    const int b  = blockIdx.z;
    const int h  = blockIdx.y;
    const int it = (int)gridDim.x - 1 - (int)blockIdx.x;  // biggest tiles first

    const int off = offsets[b];
    const int len = offsets[b + 1] - off;
    const int i0  = it * BM;
    if (i0 >= len) return;

    const int msl = p_msl ? *p_msl : 1024;
    const int ssl = p_ssl ? *p_ssl : -1;
    const float rdenom = 1.0f / (float)((ssl > 0) ? ssl : msl);

    const int tid = threadIdx.x;
    const int tmg = tid >> 4;        // 0..7  : 8-row group
    const int tm  = tmg << 3;
    const int tng = tid & 15;        // 0..15 : 4-col group (scores)
    const int tn  = tng << 2;
    const int u   = tid & 15;        // dv group (8 cols) for PV
    const int g0  = tmg << 1;        // q/p m float4-group
    const int g1  = g0 + 1;

    // loader mapping: 128 threads move 4 rows x 128 floats per iteration
    const int lrow = tid >> 5;               // 0..3
    const int lt   = tid & 31;               // 0..31
    const int ld4  = lt << 2;                // d base of float4
    const int vcol = ((((lt & 1) << 4) | (lt >> 1)) << 2); // permuted V offset

    // ---- load Q tile: transposed + swizzled ----
    {
        const float* qb = tq + (size_t)off * HD + h * DD;
        #pragma unroll
        for (int itr = 0; itr < 16; ++itr) {
            int r = (itr << 2) + lrow;
            float4 v = make_float4(0.f, 0.f, 0.f, 0.f);
            if (i0 + r < len)
                v = *(const float4*)(qb + (size_t)(i0 + r) * HD + ld4);
            // swizzled column: same for all 4 d's (d>>2 identical)
            int c = ((((r >> 2) ^ ((ld4 >> 2) & 15)) << 2) | (r & 3));
            Qt[(ld4 + 0) * 64 + c] = v.x;
            Qt[(ld4 + 1) * 64 + c] = v.y;
            Qt[(ld4 + 2) * 64 + c] = v.z;
            Qt[(ld4 + 3) * 64 + c] = v.w;
        }
    }

    // output accumulators: 8 rows x 4 f32x2 (= 8 dv cols)
    ull o2[8][4];
    #pragma unroll
    for (int i = 0; i < 8; ++i)
        #pragma unroll
        for (int j = 0; j < 4; ++j) o2[i][j] = 0ULL;

    for (int jt = 0; jt <= it; ++jt) {
        const int j0 = jt * BN;
        __syncthreads();   // prev iter's Ps/Vs reads done; Q store visible

        // ---- load K (transposed swizzled) + V (group-permuted) ----
        {
            const float* kb = tk + (size_t)off * HD + h * DD;
            const float* vb = tv + (size_t)off * HD + h * DDV;
            #pragma unroll
            for (int itr = 0; itr < 16; ++itr) {
                int r = (itr << 2) + lrow;
                float4 kv = make_float4(0.f, 0.f, 0.f, 0.f);
                float4 vv = make_float4(0.f, 0.f, 0.f, 0.f);
                if (j0 + r < len) {
                    kv = *(const float4*)(kb + (size_t)(j0 + r) * HD + ld4);
                    vv = *(const float4*)(vb + (size_t)(j0 + r) * HD + ld4);
                }
                int c = ((((r >> 2) ^ ((ld4 >> 2) & 15)) << 2) | (r & 3));
                Kt[(ld4 + 0) * 64 + c] = kv.x;
                Kt[(ld4 + 1) * 64 + c] = kv.y;
                Kt[(ld4 + 2) * 64 + c] = kv.z;
                Kt[(ld4 + 3) * 64 + c] = kv.w;
                *(float4*)(Vs + r * 128 + vcol) = vv;
            }
        }
        __syncthreads();

        // ---- scores S = Q K^T  (thread: 8m x 4n, f32x2 over row pairs) ----
        ull s2[4][4];
        #pragma unroll
        for (int p = 0; p < 4; ++p)
            #pragma unroll
            for (int n = 0; n < 4; ++n) s2[p][n] = 0ULL;

        #pragma unroll 4
        for (int k4 = 0; k4 < 128; k4 += 4) {
            const int sw = (k4 >> 2) & 15;
            const float* qp0 = Qt + k4 * 64 + ((g0  ^ sw) << 2);
            const float* qp1 = Qt + k4 * 64 + ((g1  ^ sw) << 2);
            const float* kp  = Kt + k4 * 64 + ((tng ^ sw) << 2);
            #pragma unroll
            for (int kk = 0; kk < 4; ++kk) {
                ulonglong2 qa = *(const ulonglong2*)(qp0 + kk * 64);
                ulonglong2 qb = *(const ulonglong2*)(qp1 + kk * 64);
                float4     kf = *(const float4*)(kp + kk * 64);
                ull   qv[4] = {qa.x, qa.y, qb.x, qb.y};
                float kfa[4] = {kf.x, kf.y, kf.z, kf.w};
                #pragma unroll
                for (int n = 0; n < 4; ++n) {
                    ull kd = dup2(kfa[n]);
                    #pragma unroll
                    for (int p = 0; p < 4; ++p)
                        s2[p][n] = ffma2(qv[p], kd, s2[p][n]);
                }
            }
        }

        __syncthreads();   // Kt dead from here; Ps may overwrite it

        // ---- silu + causal mask, write P^T (swizzled) ----
        #pragma unroll
        for (int n = 0; n < 4; ++n) {
            const int rj = tn + n;
            const int jg = j0 + rj;
            const int s  = (rj >> 2) & 15;
            float* prow = Ps + (rj << 6);
            #pragma unroll
            for (int p = 0; p < 4; ++p) {
                float2 v = unpk(s2[p][n]);
                const int m0 = tm + (p << 1);
                float x0 = v.x * ALPHA;
                float x1 = v.y * ALPHA;
                float p0 = (i0 + m0     >= jg)
                         ? __fdividef(x0, 1.0f + __expf(-x0)) * rdenom : 0.0f;
                float p1 = (i0 + m0 + 1 >= jg)
                         ? __fdividef(x1, 1.0f + __expf(-x1)) * rdenom : 0.0f;
                prow[((((m0      >> 2) ^ s) << 2) | ( m0      & 3))] = p0;
                prow[(((((m0 + 1) >> 2) ^ s) << 2) | ((m0 + 1) & 3))] = p1;
            }
        }
        __syncthreads();

        // ---- O += P V  (thread: 8m x 8dv, f32x2 over dv pairs) ----
        #pragma unroll 4
        for (int j = 0; j < 64; ++j) {
            const int sw = (j >> 2) & 15;
            const float* prow = Ps + (j << 6);
            float4 pa = *(const float4*)(prow + ((g0 ^ sw) << 2));
            float4 pb = *(const float4*)(prow + ((g1 ^ sw) << 2));
            const float* vrow = Vs + (j << 7);
            ulonglong2 va = *(const ulonglong2*)(vrow + (u << 2));        // dv 8u..8u+3
            ulonglong2 vb = *(const ulonglong2*)(vrow + 64 + (u << 2));   // dv 8u+4..8u+7
            float pf[8] = {pa.x, pa.y, pa.z, pa.w, pb.x, pb.y, pb.z, pb.w};
            ull   vv[4] = {va.x, va.y, vb.x, vb.y};
            #pragma unroll
            for (int m = 0; m < 8; ++m) {
                ull pd = dup2(pf[m]);
                #pragma unroll
                for (int c = 0; c < 4; ++c)
                    o2[m][c] = ffma2(pd, vv[c], o2[m][c]);
            }
        }
    }

    // ---- store O (8 rows x 8 dv per thread, two 16B stores per row) ----
    float* ob = out + (size_t)off * HD + h * DDV + (u << 3);
    #pragma unroll
    for (int m = 0; m < 8; ++m) {
        const int r = i0 + tm + m;
        if (r < len) {
            ulonglong2 w0; w0.x = o2[m][0]; w0.y = o2[m][1];
            ulonglong2 w1; w1.x = o2[m][2]; w1.y = o2[m][3];
            *(ulonglong2*)(ob + (size_t)r * HD)     = w0;
            *(ulonglong2*)(ob + (size_t)r * HD + 4) = w1;
        }
    }
}

extern "C" void kernel_launch(void* const* d_in, const int* in_sizes, int n_in,
                              void* d_out, int out_size)
{
    const float* tq      = (const float*)d_in[0];
    const float* tk      = (const float*)d_in[1];
    const float* tv      = (const float*)d_in[2];
    const int*   offsets = (const int*)  d_in[3];
    const int*   p_msl   = (n_in > 4) ? (const int*)d_in[4] : nullptr;
    const int*   p_ssl   = (n_in > 5) ? (const int*)d_in[5] : nullptr;
    float*       out     = (float*)d_out;

    const int B = in_sizes[3] - 1;           // offsets has B+1 entries
    const int smem_bytes = SMEM_FLOATS * (int)sizeof(float);   // 96 KB

    cudaFuncSetAttribute((const void*)hstu_attn_kernel,
                         cudaFuncAttributeMaxDynamicSharedMemorySize, smem_bytes);

    dim3 grid(MAXTILES, HH, B);
    hstu_attn_kernel<<<grid, NTH, smem_bytes>>>(tq, tk, tv, offsets,
                                                p_msl, p_ssl, out);
}

// round 5
// speedup vs baseline: 2.1141x; 2.1141x over previous
#include <cuda_runtime.h>
#include <stdint.h>

// HSTU jagged causal attention via mma.sync tf32 (baseline PTX, works on sm_103
// non-'a' target — tcgen05 is rejected by this build's ptxas target).
//
//   out[i] = sum_{j<=i} silu(q_i.k_j/sqrt(D))/max_seqlen * v_j   per (seq, head)
// H=8, D=DV=128, B=8, max_seqlen=1024.
//
// CTA: 64-row Q tile x (head, batch), 128 threads (4 warps x 16-row warp tile).
// Loop over 64-row K/V tiles (causal):
//   S[64x64]  = Q K^T   (m16n8k8 tf32 mma, operands from padded smem)
//   P = mask(silu(S*alpha))/denom -> smem (aliases K, which is dead)
//   O[64x128] += P V    (m16n8k8 tf32 mma, accum in registers)
// Pads: Q/K/P row stride 132 floats, V 136 -> all fragment LDS patterns
// are 32-bank conflict-free. 100KB smem -> 2 CTAs/SM.

#define HD    1024
#define BM    64
#define BN    64
#define NTH   128
#define NTILES 16
#define SQK   132          // Q/K/P row stride (floats)
#define SV    136          // V row stride (floats)
#define SMF_Q 0
#define SMF_K 8448         // 64*132
#define SMF_P 8448         // aliases K
#define SMF_V 16896        // 8448*2
#define SMEM_FLOATS 25600  // 16896 + 64*136 = 25600 -> 100KB
#define ALPHA 0.08838834764831845f

__device__ __forceinline__ uint32_t to_tf32(float f) {
    uint32_t r;
    asm("cvt.rna.tf32.f32 %0, %1;" : "=r"(r) : "f"(f));
    return r;
}
__device__ __forceinline__ void mma_tf32(float* c, const uint32_t* a,
                                         uint32_t b0, uint32_t b1) {
    asm volatile(
        "mma.sync.aligned.m16n8k8.row.col.f32.tf32.tf32.f32 "
        "{%0,%1,%2,%3}, {%4,%5,%6,%7}, {%8,%9}, {%0,%1,%2,%3};"
        : "+f"(c[0]), "+f"(c[1]), "+f"(c[2]), "+f"(c[3])
        : "r"(a[0]), "r"(a[1]), "r"(a[2]), "r"(a[3]), "r"(b0), "r"(b1));
}

__global__ void __launch_bounds__(NTH)
hstu_mma_kernel(const float* __restrict__ tq, const float* __restrict__ tk,
                const float* __restrict__ tv, const int* __restrict__ offsets,
                const int* __restrict__ p_msl, const int* __restrict__ p_ssl,
                float* __restrict__ out)
{
    extern __shared__ float sm[];
    float* Qs = sm + SMF_Q;   // [m:64][k:128] stride 132, tf32 bits
    float* Ks = sm + SMF_K;   // [n:64][k:128] stride 132
    float* Ps = sm + SMF_P;   // [m:64][j:64]  stride 132 (aliases Ks)
    float* Vs = sm + SMF_V;   // [j:64][dv:128] stride 136

    const int b  = blockIdx.z;
    const int h  = blockIdx.y;
    const int it = (int)gridDim.x - 1 - (int)blockIdx.x;   // big tiles first

    const int off = offsets[b];
    const int len = offsets[b + 1] - off;
    const int i0  = it * BM;
    if (i0 >= len) return;

    const int msl = p_msl ? *p_msl : 1024;
    const int ssl = p_ssl ? *p_ssl : -1;
    const float rdenom = 1.0f / (float)((ssl > 0) ? ssl : msl);
    const float c_a = 0.5f * ALPHA;            // tanh arg scale
    const float c_b = 0.5f * ALPHA * rdenom;   // output scale

    const int tid  = threadIdx.x;
    const int w    = tid >> 5;
    const int lane = tid & 31;
    const int g    = lane >> 2;                // group row 0..7
    const int t4   = lane & 3;                 // thread-in-group 0..3
    const int m0   = w << 4;                   // warp's 16-row base

    // ---- load Q tile (64x128 f32 -> tf32 bits in smem) ----
    {
        const float* qb = tq + (size_t)off * HD + h * 128;
        #pragma unroll
        for (int itr = 0; itr < 16; ++itr) {
            int idx = itr * NTH + tid;         // 0..2047
            int r   = idx >> 5;                // 0..63
            int c4  = idx & 31;                // float4 group
            float4 v = make_float4(0.f, 0.f, 0.f, 0.f);
            if (i0 + r < len)
                v = *(const float4*)(qb + (size_t)(i0 + r) * HD + c4 * 4);
            uint4 t;
            t.x = to_tf32(v.x); t.y = to_tf32(v.y);
            t.z = to_tf32(v.z); t.w = to_tf32(v.w);
            *(uint4*)(Qs + r * SQK + c4 * 4) = t;
        }
    }

    // output accumulators: 16 dv-frags x 4 (warp tile 16 x 128)
    float oacc[16][4];
    #pragma unroll
    for (int i = 0; i < 16; ++i)
        #pragma unroll
        for (int j = 0; j < 4; ++j) oacc[i][j] = 0.f;

    const float* kb = tk + (size_t)off * HD + h * 128;
    const float* vb = tv + (size_t)off * HD + h * 128;
    const int nj = it + 1;                     // causal tile count

    for (int jt = 0; jt < nj; ++jt) {
        const int j0 = jt * BN;
        __syncthreads();   // prev iter's P/V consumers done

        // ---- K tile -> smem [n][k], V tile -> smem [j][dv], tf32 ----
        #pragma unroll
        for (int itr = 0; itr < 16; ++itr) {
            int idx = itr * NTH + tid;
            int r   = idx >> 5;
            int c4  = idx & 31;
            float4 kv = make_float4(0.f, 0.f, 0.f, 0.f);
            float4 vv = make_float4(0.f, 0.f, 0.f, 0.f);
            if (j0 + r < len) {
                kv = *(const float4*)(kb + (size_t)(j0 + r) * HD + c4 * 4);
                vv = *(const float4*)(vb + (size_t)(j0 + r) * HD + c4 * 4);
            }
            uint4 tk4, tv4;
            tk4.x = to_tf32(kv.x); tk4.y = to_tf32(kv.y);
            tk4.z = to_tf32(kv.z); tk4.w = to_tf32(kv.w);
            tv4.x = to_tf32(vv.x); tv4.y = to_tf32(vv.y);
            tv4.z = to_tf32(vv.z); tv4.w = to_tf32(vv.w);
            *(uint4*)(Ks + r * SQK + c4 * 4) = tk4;
            *(uint4*)(Vs + r * SV  + c4 * 4) = tv4;
        }
        __syncthreads();

        // ---- score: S[16x64] per warp = Q K^T, k=128 ----
        float sacc[8][4];
        #pragma unroll
        for (int i = 0; i < 8; ++i)
            #pragma unroll
            for (int j = 0; j < 4; ++j) sacc[i][j] = 0.f;

        #pragma unroll
        for (int ks = 0; ks < 16; ++ks) {
            const int k0 = ks << 3;
            uint32_t a[4];
            const float* qa = Qs + (m0 + g) * SQK + k0 + t4;
            a[0] = __float_as_uint(qa[0]);
            a[1] = __float_as_uint(qa[8 * SQK]);
            a[2] = __float_as_uint(qa[4]);
            a[3] = __float_as_uint(qa[8 * SQK + 4]);
            #pragma unroll
            for (int nf = 0; nf < 8; ++nf) {
                const float* kp = Ks + (nf * 8 + g) * SQK + k0 + t4;
                uint32_t b0 = __float_as_uint(kp[0]);
                uint32_t b1 = __float_as_uint(kp[4]);
                mma_tf32(sacc[nf], a, b0, b1);
            }
        }
        __syncthreads();   // all warps done reading Ks; Ps may overwrite

        // ---- silu + causal mask + scale -> P (tf32 bits) ----
        {
            const int gi0 = i0 + m0 + g;       // global row (lower 8-row half)
            #pragma unroll
            for (int nf = 0; nf < 8; ++nf) {
                const int jc = j0 + nf * 8 + 2 * t4;
                float p[4];
                #pragma unroll
                for (int e = 0; e < 4; ++e) {
                    float s = sacc[nf][e];
                    float t;
                    asm("tanh.approx.f32 %0, %1;" : "=f"(t) : "f"(s * c_a));
                    float hx = s * c_b;
                    p[e] = fmaf(hx, t, hx);    // rdenom * x * sigmoid(x)
                }
                const int gi1 = gi0 + 8;
                p[0] = (gi0 >= jc)     ? p[0] : 0.f;
                p[1] = (gi0 >= jc + 1) ? p[1] : 0.f;
                p[2] = (gi1 >= jc)     ? p[2] : 0.f;
                p[3] = (gi1 >= jc + 1) ? p[3] : 0.f;
                uint32_t u0 = to_tf32(p[0]), u1 = to_tf32(p[1]);
                uint32_t u2 = to_tf32(p[2]), u3 = to_tf32(p[3]);
                float* pp = Ps + (m0 + g) * SQK + nf * 8 + 2 * t4;
                uint2 w0; w0.x = u0; w0.y = u1;
                uint2 w1; w1.x = u2; w1.y = u3;
                *(uint2*)(pp)           = w0;
                *(uint2*)(pp + 8 * SQK) = w1;
            }
        }
        __syncthreads();

        // ---- PV: O[16x128] += P[16x64] V[64x128] ----
        #pragma unroll
        for (int ks = 0; ks < 8; ++ks) {
            const int k0 = ks << 3;
            uint32_t a[4];
            const float* pa = Ps + (m0 + g) * SQK + k0 + t4;
            a[0] = __float_as_uint(pa[0]);
            a[1] = __float_as_uint(pa[8 * SQK]);
            a[2] = __float_as_uint(pa[4]);
            a[3] = __float_as_uint(pa[8 * SQK + 4]);
            const float* vr0 = Vs + (k0 + t4) * SV + g;
            const float* vr1 = vr0 + 4 * SV;
            #pragma unroll
            for (int nf = 0; nf < 16; ++nf) {
                uint32_t b0 = __float_as_uint(vr0[nf * 8]);
                uint32_t b1 = __float_as_uint(vr1[nf * 8]);
                mma_tf32(oacc[nf], a, b0, b1);
            }
        }
    }

    // ---- store O: warp tile rows m0+g / m0+g+8, 16 dv-frags ----
    {
        const int r0 = i0 + m0 + g;
        const int r1 = r0 + 8;
        float* ob0 = out + (size_t)(off + r0) * HD + h * 128 + 2 * t4;
        float* ob1 = out + (size_t)(off + r1) * HD + h * 128 + 2 * t4;
        #pragma unroll
        for (int nf = 0; nf < 16; ++nf) {
            if (r0 < len) {
                float2 v; v.x = oacc[nf][0]; v.y = oacc[nf][1];
                *(float2*)(ob0 + nf * 8) = v;
            }
            if (r1 < len) {
                float2 v; v.x = oacc[nf][2]; v.y = oacc[nf][3];
                *(float2*)(ob1 + nf * 8) = v;
            }
        }
    }
}

extern "C" void kernel_launch(void* const* d_in, const int* in_sizes, int n_in,
                              void* d_out, int out_size)
{
    const float* tq      = (const float*)d_in[0];
    const float* tk      = (const float*)d_in[1];
    const float* tv      = (const float*)d_in[2];
    const int*   offsets = (const int*)  d_in[3];
    const int*   p_msl   = (n_in > 4) ? (const int*)d_in[4] : nullptr;
    const int*   p_ssl   = (n_in > 5) ? (const int*)d_in[5] : nullptr;
    float*       out     = (float*)d_out;

    const int B = in_sizes[3] - 1;
    const int smem_bytes = SMEM_FLOATS * (int)sizeof(float);   // 100 KB

    cudaFuncSetAttribute((const void*)hstu_mma_kernel,
                         cudaFuncAttributeMaxDynamicSharedMemorySize, smem_bytes);

    dim3 grid(NTILES, 8, B);
    hstu_mma_kernel<<<grid, NTH, smem_bytes>>>(tq, tk, tv, offsets,
                                               p_msl, p_ssl, out);
}

// round 6
// speedup vs baseline: 2.9431x; 1.3922x over previous
#include <cuda_runtime.h>
#include <stdint.h>

// HSTU jagged causal attention, mma.sync tf32 + cp.async pipelined smem.
//   out[i] = sum_{j<=i} silu(q_i.k_j/sqrt(D))/max_seqlen * v_j  per (seq,head)
// H=8, D=DV=128, B=8, max_seqlen=1024.
//
// CTA: 128-row Q tile x (head, batch), 256 threads = 8 warps.
//  MMA1 (scores): warp (mh=w&3, nh=w>>2) owns m32 x n32 of S[128x64], k=128.
//  MMA2 (PV):     warp (mh, vh=w>>2)    owns m32 x dv64 of O[128x128], k=64.
// K double-buffered + V single-buffered via cp.async.cg (raw fp32; B-fragments
// cvt.rna.tf32 after LDS). Q and P are stored pre-rounded tf32 in smem.
// Strides: Q/K 132, V 136, P 68 -> all fragment LDS patterns conflict-free.
// Smem 200KB -> 1 CTA/SM.

#define HD    1024
#define BM    128
#define BN    64
#define NTH   256
#define NTILES 8          // ceil(1024/128)
#define SQK   132
#define SV    136
#define SP    68
#define SMF_Q  0          // 128*132      = 16896
#define SMF_K  16896      // 2 * 64*132   = 16896 (stages of 8448)
#define KSTG   8448
#define SMF_V  33792      // 64*136       = 8704
#define SMF_P  42496      // 128*68       = 8704
#define SMEM_FLOATS 51200 // 200 KB
#define ALPHA 0.08838834764831845f

__device__ __forceinline__ uint32_t to_tf32(float f) {
    uint32_t r;
    asm("cvt.rna.tf32.f32 %0, %1;" : "=r"(r) : "f"(f));
    return r;
}
__device__ __forceinline__ void mma_tf32(float* c, const uint32_t* a,
                                         uint32_t b0, uint32_t b1) {
    asm volatile(
        "mma.sync.aligned.m16n8k8.row.col.f32.tf32.tf32.f32 "
        "{%0,%1,%2,%3}, {%4,%5,%6,%7}, {%8,%9}, {%0,%1,%2,%3};"
        : "+f"(c[0]), "+f"(c[1]), "+f"(c[2]), "+f"(c[3])
        : "r"(a[0]), "r"(a[1]), "r"(a[2]), "r"(a[3]), "r"(b0), "r"(b1));
}
__device__ __forceinline__ uint32_t smem_u32(const void* p) {
    uint32_t a;
    asm("{ .reg .u64 t; cvta.to.shared.u64 t, %1; cvt.u32.u64 %0, t; }"
        : "=r"(a) : "l"(p));
    return a;
}
__device__ __forceinline__ void cpa16(uint32_t dst, const float* src, int srcsz) {
    asm volatile("cp.async.cg.shared.global [%0], [%1], 16, %2;"
                 :: "r"(dst), "l"(src), "r"(srcsz) : "memory");
}
#define CPA_COMMIT() asm volatile("cp.async.commit_group;" ::: "memory")
#define CPA_WAIT1()  asm volatile("cp.async.wait_group 1;" ::: "memory")

__global__ void __launch_bounds__(NTH, 1)
hstu_pipe_kernel(const float* __restrict__ tq, const float* __restrict__ tk,
                 const float* __restrict__ tv, const int* __restrict__ offsets,
                 const int* __restrict__ p_msl, const int* __restrict__ p_ssl,
                 float* __restrict__ out)
{
    extern __shared__ float smf[];
    float* Qs = smf + SMF_Q;   // tf32 bits
    float* Vs = smf + SMF_V;   // raw fp32
    float* Ps = smf + SMF_P;   // tf32 bits
    const uint32_t smu = smem_u32(smf);

    const int b  = blockIdx.z;
    const int h  = blockIdx.y;
    const int it = (int)gridDim.x - 1 - (int)blockIdx.x;   // big tiles first

    const int off = offsets[b];
    const int len = offsets[b + 1] - off;
    const int i0  = it * BM;
    if (i0 >= len) return;

    const int msl = p_msl ? *p_msl : 1024;
    const int ssl = p_ssl ? *p_ssl : -1;
    const float rdenom = 1.0f / (float)((ssl > 0) ? ssl : msl);
    const float c_a = 0.5f * ALPHA;
    const float c_b = 0.5f * ALPHA * rdenom;

    const int tid  = threadIdx.x;
    const int w    = tid >> 5;
    const int lane = tid & 31;
    const int g    = lane >> 2;
    const int t4   = lane & 3;
    const int mh   = w & 3;
    const int nh   = w >> 2;           // score n-half / PV dv-half
    const int mbase = mh << 5;
    const int nbase = nh << 5;
    const int vbase = nh << 6;

    const float* kb = tk + (size_t)off * HD + h * 128;
    const float* vb = tv + (size_t)off * HD + h * 128;

    const int nj = min(2 * it + 2, (len + BN - 1) >> 6);

    // loader indices (per cp.async batch of 2048 chunks: 8 per thread)
    const int lr = tid >> 5;           // handled inside loops via idx

    // ---- prologue: async K[0], V[0]; then Q load (overlaps) ----
    {
        #pragma unroll
        for (int i2 = 0; i2 < 8; ++i2) {
            int idx = i2 * NTH + tid;  int r = idx >> 5;  int c = idx & 31;
            int gr = r;  int ok = (gr < len) ? 16 : 0;
            cpa16(smu + (uint32_t)(SMF_K + r * SQK + c * 4) * 4,
                  kb + (size_t)(ok ? gr : 0) * HD + c * 4, ok);
        }
        CPA_COMMIT();
        #pragma unroll
        for (int i2 = 0; i2 < 8; ++i2) {
            int idx = i2 * NTH + tid;  int r = idx >> 5;  int c = idx & 31;
            int ok = (r < len) ? 16 : 0;
            cpa16(smu + (uint32_t)(SMF_V + r * SV + c * 4) * 4,
                  vb + (size_t)(ok ? r : 0) * HD + c * 4, ok);
        }
        CPA_COMMIT();

        const float* qb = tq + (size_t)off * HD + h * 128;
        #pragma unroll
        for (int i2 = 0; i2 < 16; ++i2) {
            int idx = i2 * NTH + tid;  int r = idx >> 5;  int c = idx & 31;
            float4 v = make_float4(0.f, 0.f, 0.f, 0.f);
            if (i0 + r < len)
                v = *(const float4*)(qb + (size_t)(i0 + r) * HD + c * 4);
            uint4 t;
            t.x = to_tf32(v.x); t.y = to_tf32(v.y);
            t.z = to_tf32(v.z); t.w = to_tf32(v.w);
            *(uint4*)(Qs + r * SQK + c * 4) = t;
        }
    }

    float oacc[2][8][4];
    #pragma unroll
    for (int a = 0; a < 2; ++a)
        #pragma unroll
        for (int bn = 0; bn < 8; ++bn)
            #pragma unroll
            for (int e = 0; e < 4; ++e) oacc[a][bn][e] = 0.f;

    (void)lr;

    for (int jt = 0; jt < nj; ++jt) {
        const int j0 = jt * BN;
        const int st = jt & 1;
        const float* Kc = smf + SMF_K + st * KSTG;   // raw fp32 K tile

        CPA_WAIT1();            // K[jt] landed (V[jt] may still be in flight)
        __syncthreads();

        // prefetch K[jt+1] into other stage
        if (jt + 1 < nj) {
            const int j1 = j0 + BN;
            const int os = (SMF_K + (st ^ 1) * KSTG);
            #pragma unroll
            for (int i2 = 0; i2 < 8; ++i2) {
                int idx = i2 * NTH + tid;  int r = idx >> 5;  int c = idx & 31;
                int gr = j1 + r;  int ok = (gr < len) ? 16 : 0;
                cpa16(smu + (uint32_t)(os + r * SQK + c * 4) * 4,
                      kb + (size_t)(ok ? gr : 0) * HD + c * 4, ok);
            }
        }
        CPA_COMMIT();

        // ---- MMA1: warp m32 x n32, k=128 ----
        float sacc[2][4][4];
        #pragma unroll
        for (int a = 0; a < 2; ++a)
            #pragma unroll
            for (int bn = 0; bn < 4; ++bn)
                #pragma unroll
                for (int e = 0; e < 4; ++e) sacc[a][bn][e] = 0.f;

        #pragma unroll
        for (int ks = 0; ks < 16; ++ks) {
            const int k0 = ks << 3;
            uint32_t a[2][4];
            #pragma unroll
            for (int mf = 0; mf < 2; ++mf) {
                const float* qa = Qs + (mbase + mf * 16 + g) * SQK + k0 + t4;
                a[mf][0] = __float_as_uint(qa[0]);
                a[mf][1] = __float_as_uint(qa[8 * SQK]);
                a[mf][2] = __float_as_uint(qa[4]);
                a[mf][3] = __float_as_uint(qa[8 * SQK + 4]);
            }
            #pragma unroll
            for (int nf = 0; nf < 4; ++nf) {
                const float* kp = Kc + (nbase + nf * 8 + g) * SQK + k0 + t4;
                uint32_t b0 = to_tf32(kp[0]);
                uint32_t b1 = to_tf32(kp[4]);
                mma_tf32(sacc[0][nf], a[0], b0, b1);
                mma_tf32(sacc[1][nf], a[1], b0, b1);
            }
        }

        // ---- silu + causal + scale -> Ps (tf32) ----
        #pragma unroll
        for (int mf = 0; mf < 2; ++mf) {
            const int r0 = mbase + mf * 16 + g;
            const int gi0 = i0 + r0;
            #pragma unroll
            for (int nf = 0; nf < 4; ++nf) {
                const int jc = j0 + nbase + nf * 8 + 2 * t4;
                float p[4];
                #pragma unroll
                for (int e = 0; e < 4; ++e) {
                    float s = sacc[mf][nf][e];
                    float t;
                    asm("tanh.approx.f32 %0, %1;" : "=f"(t) : "f"(s * c_a));
                    float hx = s * c_b;
                    p[e] = fmaf(hx, t, hx);
                }
                p[0] = (gi0     >= jc)     ? p[0] : 0.f;
                p[1] = (gi0     >= jc + 1) ? p[1] : 0.f;
                p[2] = (gi0 + 8 >= jc)     ? p[2] : 0.f;
                p[3] = (gi0 + 8 >= jc + 1) ? p[3] : 0.f;
                float* pp = Ps + r0 * SP + nbase + nf * 8 + 2 * t4;
                uint2 w0; w0.x = to_tf32(p[0]); w0.y = to_tf32(p[1]);
                uint2 w1; w1.x = to_tf32(p[2]); w1.y = to_tf32(p[3]);
                *(uint2*)(pp)          = w0;
                *(uint2*)(pp + 8 * SP) = w1;
            }
        }

        CPA_WAIT1();            // V[jt] landed (only K[jt+1] may pend)
        __syncthreads();        // P visible + V visible

        // ---- MMA2: warp m32 x dv64, k = 64 (j) ----
        #pragma unroll
        for (int ks = 0; ks < 8; ++ks) {
            const int k0 = ks << 3;
            uint32_t a[2][4];
            #pragma unroll
            for (int mf = 0; mf < 2; ++mf) {
                const float* pa = Ps + (mbase + mf * 16 + g) * SP + k0 + t4;
                a[mf][0] = __float_as_uint(pa[0]);
                a[mf][1] = __float_as_uint(pa[8 * SP]);
                a[mf][2] = __float_as_uint(pa[4]);
                a[mf][3] = __float_as_uint(pa[8 * SP + 4]);
            }
            const float* vr = Vs + (k0 + t4) * SV + vbase + g;
            #pragma unroll
            for (int nf = 0; nf < 8; ++nf) {
                uint32_t b0 = to_tf32(vr[nf * 8]);
                uint32_t b1 = to_tf32(vr[nf * 8 + 4 * SV]);
                mma_tf32(oacc[0][nf], a[0], b0, b1);
                mma_tf32(oacc[1][nf], a[1], b0, b1);
            }
        }

        __syncthreads();        // all warps done reading V[jt]

        if (jt + 1 < nj) {
            const int j1 = j0 + BN;
            #pragma unroll
            for (int i2 = 0; i2 < 8; ++i2) {
                int idx = i2 * NTH + tid;  int r = idx >> 5;  int c = idx & 31;
                int gr = j1 + r;  int ok = (gr < len) ? 16 : 0;
                cpa16(smu + (uint32_t)(SMF_V + r * SV + c * 4) * 4,
                      vb + (size_t)(ok ? gr : 0) * HD + c * 4, ok);
            }
        }
        CPA_COMMIT();
    }

    // ---- store O ----
    #pragma unroll
    for (int mf = 0; mf < 2; ++mf) {
        const int r0 = i0 + mbase + mf * 16 + g;
        const int r1 = r0 + 8;
        float* ob0 = out + (size_t)(off + r0) * HD + h * 128 + vbase + 2 * t4;
        float* ob1 = out + (size_t)(off + r1) * HD + h * 128 + vbase + 2 * t4;
        #pragma unroll
        for (int nf = 0; nf < 8; ++nf) {
            if (r0 < len) {
                float2 v; v.x = oacc[mf][nf][0]; v.y = oacc[mf][nf][1];
                *(float2*)(ob0 + nf * 8) = v;
            }
            if (r1 < len) {
                float2 v; v.x = oacc[mf][nf][2]; v.y = oacc[mf][nf][3];
                *(float2*)(ob1 + nf * 8) = v;
            }
        }
    }
}

extern "C" void kernel_launch(void* const* d_in, const int* in_sizes, int n_in,
                              void* d_out, int out_size)
{
    const float* tq      = (const float*)d_in[0];
    const float* tk      = (const float*)d_in[1];
    const float* tv      = (const float*)d_in[2];
    const int*   offsets = (const int*)  d_in[3];
    const int*   p_msl   = (n_in > 4) ? (const int*)d_in[4] : nullptr;
    const int*   p_ssl   = (n_in > 5) ? (const int*)d_in[5] : nullptr;
    float*       out     = (float*)d_out;

    const int B = in_sizes[3] - 1;
    const int smem_bytes = SMEM_FLOATS * (int)sizeof(float);   // 200 KB

    cudaFuncSetAttribute((const void*)hstu_pipe_kernel,
                         cudaFuncAttributeMaxDynamicSharedMemorySize, smem_bytes);

    dim3 grid(NTILES, 8, B);
    hstu_pipe_kernel<<<grid, NTH, smem_bytes>>>(tq, tk, tv, offsets,
                                                p_msl, p_ssl, out);
}

// round 7
// speedup vs baseline: 3.3461x; 1.1369x over previous
#include <cuda_runtime.h>
#include <stdint.h>

// HSTU jagged causal attention — mma.sync tf32, cp.async pipelined,
// XOR-swizzled (pad-free) smem so 2 CTAs fit per SM (112KB each).
//   out[i] = sum_{j<=i} silu(q_i.k_j/sqrt(D))/max_seqlen * v_j  per (seq,head)
// H=8, D=DV=128, B=8, max_seqlen=1024.
//
// CTA: 64-row Q tile x (head,batch), 128 threads = 4 warps.
//  MMA1: warp (mh=w&1, nh=w>>1) -> m32 x n32 of S[64x64], k=128.
//  MMA2: warp (mh, vh=w>>1)     -> m32 x dv64 of O[64x128], k=64.
// Layouts (16B chunks, swizzle on chunk index):
//  Q [m64][k128] tf32-bits,  chunk' = c ^ (m&7)    (A-pattern, conflict-free)
//  K [n64][k128] raw fp32,   chunk' = c ^ (n&7)    (B-pattern-K, conflict-free)
//  V [j64][dv128] raw fp32,  chunk' = c ^ ((j&3)<<1) (B-pattern-V, conflict-free)
//  P [m64][j64]  tf32-bits,  chunk' = c ^ (m&7)    (A-pattern; 2-way on STS.64)
// cp.async: K[jt+1] prefetched after MMA1 (buffer free), V[jt+1] after MMA2;
// group-count invariant kept with unconditional commits; wait_group 1 at uses.

#define HD    1024
#define NTH   128
#define BM    64
#define BN    64
#define NTILES 15
#define ALPHA 0.08838834764831845f

// smem (floats)
#define SF_Q 0
#define SF_K 8192
#define SF_V 16384
#define SF_P 24576
#define SMEM_FLOATS 28672          // 112 KB
// byte offsets
#define SB_K 32768
#define SB_V 65536

__device__ __forceinline__ uint32_t to_tf32(float f) {
    uint32_t r;
    asm("cvt.rna.tf32.f32 %0, %1;" : "=r"(r) : "f"(f));
    return r;
}
__device__ __forceinline__ void mma_tf32(float* c, const uint32_t* a,
                                         uint32_t b0, uint32_t b1) {
    asm volatile(
        "mma.sync.aligned.m16n8k8.row.col.f32.tf32.tf32.f32 "
        "{%0,%1,%2,%3}, {%4,%5,%6,%7}, {%8,%9}, {%0,%1,%2,%3};"
        : "+f"(c[0]), "+f"(c[1]), "+f"(c[2]), "+f"(c[3])
        : "r"(a[0]), "r"(a[1]), "r"(a[2]), "r"(a[3]), "r"(b0), "r"(b1));
}
__device__ __forceinline__ uint32_t smem_u32(const void* p) {
    uint32_t a;
    asm("{ .reg .u64 t; cvta.to.shared.u64 t, %1; cvt.u32.u64 %0, t; }"
        : "=r"(a) : "l"(p));
    return a;
}
__device__ __forceinline__ void cpa16(uint32_t dst, const float* src, int srcsz) {
    asm volatile("cp.async.cg.shared.global [%0], [%1], 16, %2;"
                 :: "r"(dst), "l"(src), "r"(srcsz) : "memory");
}
#define CPA_COMMIT() asm volatile("cp.async.commit_group;" ::: "memory")
#define CPA_WAIT1()  asm volatile("cp.async.wait_group 1;" ::: "memory")

__global__ void __launch_bounds__(NTH, 2)
hstu_occ_kernel(const float* __restrict__ tq, const float* __restrict__ tk,
                const float* __restrict__ tv, const int* __restrict__ offsets,
                const int* __restrict__ p_msl, const int* __restrict__ p_ssl,
                float* __restrict__ out)
{
    extern __shared__ float smf[];
    float* Qs = smf + SF_Q;
    float* Ks = smf + SF_K;
    float* Vs = smf + SF_V;
    float* Ps = smf + SF_P;
    const uint32_t smu = smem_u32(smf);

    const int b  = blockIdx.z;
    const int h  = blockIdx.y;
    const int it = (int)gridDim.x - 1 - (int)blockIdx.x;   // big tiles first

    const int off = offsets[b];
    const int len = offsets[b + 1] - off;
    const int i0  = it * BM;
    if (i0 >= len) return;

    const int msl = p_msl ? *p_msl : 1024;
    const int ssl = p_ssl ? *p_ssl : -1;
    const float rdenom = 1.0f / (float)((ssl > 0) ? ssl : msl);
    const float c_a = 0.5f * ALPHA;
    const float c_b = 0.5f * ALPHA * rdenom;

    const int tid  = threadIdx.x;
    const int w    = tid >> 5;
    const int lane = tid & 31;
    const int g    = lane >> 2;       // 0..7
    const int t4   = lane & 3;        // 0..3
    const int g3   = g & 3;
    const int gh   = g >> 2;
    const int mh   = w & 1;
    const int nh   = w >> 1;
    const int mbase = mh << 5;
    const int nbase = nh << 5;        // MMA1 n-half
    const int vbase = nh << 6;        // MMA2 dv-half
    const int vb2   = vbase >> 2;     // dv chunk base
    const int xv    = t4 << 1;        // V swizzle term ((j&3)<<1, j=8ks+t4)

    const float* kb = tk + (size_t)off * HD + h * 128;
    const float* vb = tv + (size_t)off * HD + h * 128;

    const int nj = it + 1;            // causal: all j-tiles <= i-tile are in-range

    // loader lambda-ish: each thread moves 16 chunks (64 rows x 32 chunks)
    // K swizzle c^(r&7); V swizzle c^((r&3)<<1).

    // ---- prologue: async K[0], V[0]; Q load (LDG->tf32->swizzled STS.128) ----
    {
        #pragma unroll
        for (int i2 = 0; i2 < 16; ++i2) {
            int idx = i2 * NTH + tid;  int r = idx >> 5;  int c = idx & 31;
            int ok = (r < len) ? 16 : 0;
            cpa16(smu + SB_K + (uint32_t)(r * 512 + (c ^ (r & 7)) * 16),
                  kb + (size_t)(ok ? r : 0) * HD + c * 4, ok);
        }
        CPA_COMMIT();
        #pragma unroll
        for (int i2 = 0; i2 < 16; ++i2) {
            int idx = i2 * NTH + tid;  int r = idx >> 5;  int c = idx & 31;
            int ok = (r < len) ? 16 : 0;
            cpa16(smu + SB_V + (uint32_t)(r * 512 + (c ^ ((r & 3) << 1)) * 16),
                  vb + (size_t)(ok ? r : 0) * HD + c * 4, ok);
        }
        CPA_COMMIT();

        const float* qb = tq + (size_t)off * HD + h * 128;
        #pragma unroll
        for (int i2 = 0; i2 < 16; ++i2) {
            int idx = i2 * NTH + tid;  int r = idx >> 5;  int c = idx & 31;
            float4 v = make_float4(0.f, 0.f, 0.f, 0.f);
            if (i0 + r < len)
                v = *(const float4*)(qb + (size_t)(i0 + r) * HD + c * 4);
            uint4 t;
            t.x = to_tf32(v.x); t.y = to_tf32(v.y);
            t.z = to_tf32(v.z); t.w = to_tf32(v.w);
            *(uint4*)(Qs + r * 128 + (c ^ (r & 7)) * 4) = t;
        }
    }

    float oacc[2][8][4];
    #pragma unroll
    for (int a = 0; a < 2; ++a)
        #pragma unroll
        for (int n = 0; n < 8; ++n)
            #pragma unroll
            for (int e = 0; e < 4; ++e) oacc[a][n][e] = 0.f;

    for (int jt = 0; jt < nj; ++jt) {
        const int j0 = jt * BN;

        CPA_WAIT1();               // K[jt] landed (V[jt] may pend)
        __syncthreads();

        // ---- MMA1: S[m32 x n32] = Q K^T, k=128 ----
        float sacc[2][4][4];
        #pragma unroll
        for (int a = 0; a < 2; ++a)
            #pragma unroll
            for (int n = 0; n < 4; ++n)
                #pragma unroll
                for (int e = 0; e < 4; ++e) sacc[a][n][e] = 0.f;

        #pragma unroll
        for (int ks = 0; ks < 16; ++ks) {
            const int o0 = ((2 * ks) ^ g) * 4 + t4;        // k_lo chunk offset
            const int o1 = ((2 * ks + 1) ^ g) * 4 + t4;    // k_hi chunk offset
            uint32_t a[2][4];
            #pragma unroll
            for (int mf = 0; mf < 2; ++mf) {
                const float* qa = Qs + (mbase + mf * 16 + g) * 128;
                a[mf][0] = __float_as_uint(qa[o0]);
                a[mf][1] = __float_as_uint(qa[o0 + 8 * 128]);
                a[mf][2] = __float_as_uint(qa[o1]);
                a[mf][3] = __float_as_uint(qa[o1 + 8 * 128]);
            }
            #pragma unroll
            for (int nf = 0; nf < 4; ++nf) {
                const float* kp = Ks + (nbase + 8 * nf + g) * 128;
                uint32_t b0 = to_tf32(kp[o0]);
                uint32_t b1 = to_tf32(kp[o1]);
                mma_tf32(sacc[0][nf], a[0], b0, b1);
                mma_tf32(sacc[1][nf], a[1], b0, b1);
            }
        }
        __syncthreads();           // all warps done reading K[jt]

        // prefetch K[jt+1] into the (now free) K buffer
        if (jt + 1 < nj) {
            const int j1 = j0 + BN;
            #pragma unroll
            for (int i2 = 0; i2 < 16; ++i2) {
                int idx = i2 * NTH + tid;  int r = idx >> 5;  int c = idx & 31;
                int gr = j1 + r;  int ok = (gr < len) ? 16 : 0;
                cpa16(smu + SB_K + (uint32_t)(r * 512 + (c ^ (r & 7)) * 16),
                      kb + (size_t)(ok ? gr : 0) * HD + c * 4, ok);
            }
        }
        CPA_COMMIT();

        // ---- silu + causal + scale -> P (tf32 bits, swizzled STS.64) ----
        #pragma unroll
        for (int mf = 0; mf < 2; ++mf) {
            const int r0  = mbase + mf * 16 + g;
            const int gi0 = i0 + r0;
            #pragma unroll
            for (int nf = 0; nf < 4; ++nf) {
                const int jl = nbase + 8 * nf + 2 * t4;    // local col
                const int jc = j0 + jl;                    // global col
                float p[4];
                #pragma unroll
                for (int e = 0; e < 4; ++e) {
                    float s = sacc[mf][nf][e];
                    float t;
                    asm("tanh.approx.f32 %0, %1;" : "=f"(t) : "f"(s * c_a));
                    float hx = s * c_b;
                    p[e] = fmaf(hx, t, hx);
                }
                p[0] = (gi0     >= jc)     ? p[0] : 0.f;
                p[1] = (gi0     >= jc + 1) ? p[1] : 0.f;
                p[2] = (gi0 + 8 >= jc)     ? p[2] : 0.f;
                p[3] = (gi0 + 8 >= jc + 1) ? p[3] : 0.f;
                const int cs = ((jl >> 2) ^ g) * 4 + (jl & 3);
                uint2 w0; w0.x = to_tf32(p[0]); w0.y = to_tf32(p[1]);
                uint2 w1; w1.x = to_tf32(p[2]); w1.y = to_tf32(p[3]);
                *(uint2*)(Ps + r0 * 64 + cs)       = w0;
                *(uint2*)(Ps + (r0 + 8) * 64 + cs) = w1;
            }
        }

        CPA_WAIT1();               // V[jt] landed (K[jt+1] may pend)
        __syncthreads();           // P + V visible

        // ---- MMA2: O[m32 x dv64] += P V, k=64 ----
        #pragma unroll
        for (int ks = 0; ks < 8; ++ks) {
            const int o0 = ((2 * ks) ^ g) * 4 + t4;
            const int o1 = ((2 * ks + 1) ^ g) * 4 + t4;
            uint32_t a[2][4];
            #pragma unroll
            for (int mf = 0; mf < 2; ++mf) {
                const float* pa = Ps + (mbase + mf * 16 + g) * 64;
                a[mf][0] = __float_as_uint(pa[o0]);
                a[mf][1] = __float_as_uint(pa[o0 + 8 * 64]);
                a[mf][2] = __float_as_uint(pa[o1]);
                a[mf][3] = __float_as_uint(pa[o1 + 8 * 64]);
            }
            const float* vr  = Vs + (8 * ks + t4) * 128;   // row j = 8ks+t4
            const float* vr4 = vr + 4 * 128;               // row j+4
            #pragma unroll
            for (int nf = 0; nf < 8; ++nf) {
                const int vo = ((vb2 + 2 * nf + gh) ^ xv) * 4 + g3;
                uint32_t b0 = to_tf32(vr[vo]);
                uint32_t b1 = to_tf32(vr4[vo]);
                mma_tf32(oacc[0][nf], a[0], b0, b1);
                mma_tf32(oacc[1][nf], a[1], b0, b1);
            }
        }
        __syncthreads();           // all warps done reading V[jt]

        // prefetch V[jt+1]
        if (jt + 1 < nj) {
            const int j1 = j0 + BN;
            #pragma unroll
            for (int i2 = 0; i2 < 16; ++i2) {
                int idx = i2 * NTH + tid;  int r = idx >> 5;  int c = idx & 31;
                int gr = j1 + r;  int ok = (gr < len) ? 16 : 0;
                cpa16(smu + SB_V + (uint32_t)(r * 512 + (c ^ ((r & 3) << 1)) * 16),
                      vb + (size_t)(ok ? gr : 0) * HD + c * 4, ok);
            }
        }
        CPA_COMMIT();
    }

    // ---- store O ----
    #pragma unroll
    for (int mf = 0; mf < 2; ++mf) {
        const int r0 = i0 + mbase + mf * 16 + g;
        const int r1 = r0 + 8;
        float* ob0 = out + (size_t)(off + r0) * HD + h * 128 + vbase + 2 * t4;
        float* ob1 = out + (size_t)(off + r1) * HD + h * 128 + vbase + 2 * t4;
        #pragma unroll
        for (int nf = 0; nf < 8; ++nf) {
            if (r0 < len) {
                float2 v; v.x = oacc[mf][nf][0]; v.y = oacc[mf][nf][1];
                *(float2*)(ob0 + nf * 8) = v;
            }
            if (r1 < len) {
                float2 v; v.x = oacc[mf][nf][2]; v.y = oacc[mf][nf][3];
                *(float2*)(ob1 + nf * 8) = v;
            }
        }
    }
}

extern "C" void kernel_launch(void* const* d_in, const int* in_sizes, int n_in,
                              void* d_out, int out_size)
{
    const float* tq      = (const float*)d_in[0];
    const float* tk      = (const float*)d_in[1];
    const float* tv      = (const float*)d_in[2];
    const int*   offsets = (const int*)  d_in[3];
    const int*   p_msl   = (n_in > 4) ? (const int*)d_in[4] : nullptr;
    const int*   p_ssl   = (n_in > 5) ? (const int*)d_in[5] : nullptr;
    float*       out     = (float*)d_out;

    const int B = in_sizes[3] - 1;
    const int smem_bytes = SMEM_FLOATS * (int)sizeof(float);   // 112 KB

    cudaFuncSetAttribute((const void*)hstu_occ_kernel,
                         cudaFuncAttributeMaxDynamicSharedMemorySize, smem_bytes);

    dim3 grid(NTILES, 8, B);
    hstu_occ_kernel<<<grid, NTH, smem_bytes>>>(tq, tk, tv, offsets,
                                               p_msl, p_ssl, out);
}

// round 8
// speedup vs baseline: 3.8743x; 1.1578x over previous
#include <cuda_runtime.h>
#include <stdint.h>

// HSTU jagged causal attention — mma.sync tf32 + ldmatrix fragments +
// cp.async pipeline, XOR-swizzled pad-free smem, 2 CTAs/SM (112KB each).
//   out[i] = sum_{j<=i} silu(q_i.k_j/sqrt(D))/max_seqlen * v_j  per (seq,head)
// H=8, D=DV=128, B=8, max_seqlen=1024.
//
// CTA: 64-row Q tile x (head,batch), 128 threads = 4 warps.
//  MMA1: warp (mh=w&1, nh=w>>1) -> m32 x n32 of S[64x64], k=128.
//  MMA2: warp (mh, vh=w>>1)     -> m32 x dv64 of O[64x128], k=64.
// Fragment feeds:
//  Q/P (A) and K (B) via ldmatrix.m8n8.x4 (16B chunk == ldmatrix row).
//  V (B) via scalar LDS.32 (32-bit data can't use ldmatrix.trans).
// K and V are fed to the tf32 MMA as RAW fp32 bits (HW truncates to tf32);
// Q and P are RNA-rounded once at store. Layout swizzles (16B chunk index):
//  Q/K/P: chunk' = c ^ (row&7);  V: chunk' = c ^ ((row&3)<<1).

#define HD    1024
#define NTH   128
#define BM    64
#define BN    64
#define NTILES 15
#define ALPHA 0.08838834764831845f

// smem float offsets
#define SF_Q 0
#define SF_K 8192
#define SF_V 16384
#define SF_P 24576
#define SMEM_FLOATS 28672          // 112 KB
// smem byte offsets
#define SB_K 32768
#define SB_V 65536
#define SB_P 98304

__device__ __forceinline__ uint32_t to_tf32(float f) {
    uint32_t r;
    asm("cvt.rna.tf32.f32 %0, %1;" : "=r"(r) : "f"(f));
    return r;
}
__device__ __forceinline__ void mma_tf32(float* c, const uint32_t* a,
                                         uint32_t b0, uint32_t b1) {
    asm volatile(
        "mma.sync.aligned.m16n8k8.row.col.f32.tf32.tf32.f32 "
        "{%0,%1,%2,%3}, {%4,%5,%6,%7}, {%8,%9}, {%0,%1,%2,%3};"
        : "+f"(c[0]), "+f"(c[1]), "+f"(c[2]), "+f"(c[3])
        : "r"(a[0]), "r"(a[1]), "r"(a[2]), "r"(a[3]), "r"(b0), "r"(b1));
}
__device__ __forceinline__ void ldsm4(uint32_t* d, uint32_t addr) {
    asm volatile("ldmatrix.sync.aligned.m8n8.x4.shared.b16 {%0,%1,%2,%3}, [%4];"
                 : "=r"(d[0]), "=r"(d[1]), "=r"(d[2]), "=r"(d[3]) : "r"(addr));
}
__device__ __forceinline__ uint32_t smem_u32(const void* p) {
    uint32_t a;
    asm("{ .reg .u64 t; cvta.to.shared.u64 t, %1; cvt.u32.u64 %0, t; }"
        : "=r"(a) : "l"(p));
    return a;
}
__device__ __forceinline__ void cpa16(uint32_t dst, const float* src, int srcsz) {
    asm volatile("cp.async.cg.shared.global [%0], [%1], 16, %2;"
                 :: "r"(dst), "l"(src), "r"(srcsz) : "memory");
}
#define CPA_COMMIT() asm volatile("cp.async.commit_group;" ::: "memory")
#define CPA_WAIT1()  asm volatile("cp.async.wait_group 1;" ::: "memory")

__global__ void __launch_bounds__(NTH, 2)
hstu_ldsm_kernel(const float* __restrict__ tq, const float* __restrict__ tk,
                 const float* __restrict__ tv, const int* __restrict__ offsets,
                 const int* __restrict__ p_msl, const int* __restrict__ p_ssl,
                 float* __restrict__ out)
{
    extern __shared__ float smf[];
    float* Qs = smf + SF_Q;
    float* Vs = smf + SF_V;
    float* Ps = smf + SF_P;
    const uint32_t smu = smem_u32(smf);

    const int b  = blockIdx.z;
    const int h  = blockIdx.y;
    const int it = (int)gridDim.x - 1 - (int)blockIdx.x;   // big tiles first

    const int off = offsets[b];
    const int len = offsets[b + 1] - off;
    const int i0  = it * BM;
    if (i0 >= len) return;

    const int msl = p_msl ? *p_msl : 1024;
    const int ssl = p_ssl ? *p_ssl : -1;
    const float rdenom = 1.0f / (float)((ssl > 0) ? ssl : msl);
    const float c_a = 0.5f * ALPHA;
    const float c_b = 0.5f * ALPHA * rdenom;

    const int tid  = threadIdx.x;
    const int w    = tid >> 5;
    const int lane = tid & 31;
    const int g    = lane >> 2;       // 0..7
    const int t4   = lane & 3;        // 0..3
    const int g3   = g & 3;
    const int gh   = g >> 2;
    const int mh   = w & 1;
    const int nh   = w >> 1;
    const int mbase = mh << 5;
    const int nbase = nh << 5;        // MMA1 n-half
    const int vbase = nh << 6;        // MMA2 dv-half
    const int vb2   = vbase >> 2;
    const int xv    = t4 << 1;

    // ldmatrix per-lane row addressing (xor term == lane&7 for all operands)
    const int lr = lane & 7;
    const int lq = lane >> 3;          // quad 0..3
    const int ac = lq >> 1;            // A chunk add (Q/P)
    const int kc = lq & 1;             // B chunk add (K)
    const int arow0 = mbase + ((lq & 1) << 3) + lr;       // A rows, mf=0
    const int arow1 = arow0 + 16;                          // mf=1
    const int krow0 = nbase + ((lq >> 1) << 3) + lr;      // K rows, pair 0
    const int krow1 = krow0 + 16;                          // pair 1
    const uint32_t qA0 = smu + (uint32_t)arow0 * 512;
    const uint32_t qA1 = smu + (uint32_t)arow1 * 512;
    const uint32_t kB0 = smu + SB_K + (uint32_t)krow0 * 512;
    const uint32_t kB1 = smu + SB_K + (uint32_t)krow1 * 512;
    const uint32_t pA0 = smu + SB_P + (uint32_t)arow0 * 256;
    const uint32_t pA1 = smu + SB_P + (uint32_t)arow1 * 256;

    const float* kb = tk + (size_t)off * HD + h * 128;
    const float* vb = tv + (size_t)off * HD + h * 128;
    const int nj = it + 1;

    // ---- prologue: async K[0], V[0]; Q load (LDG -> RNA tf32 -> STS.128) ----
    {
        #pragma unroll
        for (int i2 = 0; i2 < 16; ++i2) {
            int idx = i2 * NTH + tid;  int r = idx >> 5;  int c = idx & 31;
            int ok = (r < len) ? 16 : 0;
            cpa16(smu + SB_K + (uint32_t)(r * 512 + (c ^ (r & 7)) * 16),
                  kb + (size_t)(ok ? r : 0) * HD + c * 4, ok);
        }
        CPA_COMMIT();
        #pragma unroll
        for (int i2 = 0; i2 < 16; ++i2) {
            int idx = i2 * NTH + tid;  int r = idx >> 5;  int c = idx & 31;
            int ok = (r < len) ? 16 : 0;
            cpa16(smu + SB_V + (uint32_t)(r * 512 + (c ^ ((r & 3) << 1)) * 16),
                  vb + (size_t)(ok ? r : 0) * HD + c * 4, ok);
        }
        CPA_COMMIT();

        const float* qb = tq + (size_t)off * HD + h * 128;
        #pragma unroll
        for (int i2 = 0; i2 < 16; ++i2) {
            int idx = i2 * NTH + tid;  int r = idx >> 5;  int c = idx & 31;
            float4 v = make_float4(0.f, 0.f, 0.f, 0.f);
            if (i0 + r < len)
                v = *(const float4*)(qb + (size_t)(i0 + r) * HD + c * 4);
            uint4 t;
            t.x = to_tf32(v.x); t.y = to_tf32(v.y);
            t.z = to_tf32(v.z); t.w = to_tf32(v.w);
            *(uint4*)(Qs + r * 128 + (c ^ (r & 7)) * 4) = t;
        }
    }

    float oacc[2][8][4];
    #pragma unroll
    for (int a = 0; a < 2; ++a)
        #pragma unroll
        for (int n = 0; n < 8; ++n)
            #pragma unroll
            for (int e = 0; e < 4; ++e) oacc[a][n][e] = 0.f;

    for (int jt = 0; jt < nj; ++jt) {
        const int j0 = jt * BN;

        CPA_WAIT1();               // K[jt] landed
        __syncthreads();

        // ---- MMA1: S[m32 x n32] = Q K^T, k=128 (ldmatrix feeds) ----
        float sacc[2][4][4];
        #pragma unroll
        for (int a = 0; a < 2; ++a)
            #pragma unroll
            for (int n = 0; n < 4; ++n)
                #pragma unroll
                for (int e = 0; e < 4; ++e) sacc[a][n][e] = 0.f;

        #pragma unroll
        for (int ks = 0; ks < 16; ++ks) {
            const int c2 = 2 * ks;
            uint32_t a0[4], a1[4], bb0[4], bb1[4];
            ldsm4(a0,  qA0 + (uint32_t)(((c2 + ac) ^ lr) << 4));
            ldsm4(a1,  qA1 + (uint32_t)(((c2 + ac) ^ lr) << 4));
            ldsm4(bb0, kB0 + (uint32_t)(((c2 + kc) ^ lr) << 4));
            ldsm4(bb1, kB1 + (uint32_t)(((c2 + kc) ^ lr) << 4));
            mma_tf32(sacc[0][0], a0, bb0[0], bb0[1]);
            mma_tf32(sacc[0][1], a0, bb0[2], bb0[3]);
            mma_tf32(sacc[0][2], a0, bb1[0], bb1[1]);
            mma_tf32(sacc[0][3], a0, bb1[2], bb1[3]);
            mma_tf32(sacc[1][0], a1, bb0[0], bb0[1]);
            mma_tf32(sacc[1][1], a1, bb0[2], bb0[3]);
            mma_tf32(sacc[1][2], a1, bb1[0], bb1[1]);
            mma_tf32(sacc[1][3], a1, bb1[2], bb1[3]);
        }
        __syncthreads();           // all warps done reading K[jt]

        // prefetch K[jt+1]
        if (jt + 1 < nj) {
            const int j1 = j0 + BN;
            #pragma unroll
            for (int i2 = 0; i2 < 16; ++i2) {
                int idx = i2 * NTH + tid;  int r = idx >> 5;  int c = idx & 31;
                int gr = j1 + r;  int ok = (gr < len) ? 16 : 0;
                cpa16(smu + SB_K + (uint32_t)(r * 512 + (c ^ (r & 7)) * 16),
                      kb + (size_t)(ok ? gr : 0) * HD + c * 4, ok);
            }
        }
        CPA_COMMIT();

        // ---- silu + causal + scale -> P (RNA tf32, swizzled STS.64) ----
        #pragma unroll
        for (int mf = 0; mf < 2; ++mf) {
            const int r0  = mbase + mf * 16 + g;
            const int gi0 = i0 + r0;
            #pragma unroll
            for (int nf = 0; nf < 4; ++nf) {
                const int jl = nbase + 8 * nf + 2 * t4;
                const int jc = j0 + jl;
                float p[4];
                #pragma unroll
                for (int e = 0; e < 4; ++e) {
                    float s = sacc[mf][nf][e];
                    float t;
                    asm("tanh.approx.f32 %0, %1;" : "=f"(t) : "f"(s * c_a));
                    float hx = s * c_b;
                    p[e] = fmaf(hx, t, hx);
                }
                p[0] = (gi0     >= jc)     ? p[0] : 0.f;
                p[1] = (gi0     >= jc + 1) ? p[1] : 0.f;
                p[2] = (gi0 + 8 >= jc)     ? p[2] : 0.f;
                p[3] = (gi0 + 8 >= jc + 1) ? p[3] : 0.f;
                const int cs = ((jl >> 2) ^ g) * 4 + (jl & 3);
                uint2 w0; w0.x = to_tf32(p[0]); w0.y = to_tf32(p[1]);
                uint2 w1; w1.x = to_tf32(p[2]); w1.y = to_tf32(p[3]);
                *(uint2*)(Ps + r0 * 64 + cs)       = w0;
                *(uint2*)(Ps + (r0 + 8) * 64 + cs) = w1;
            }
        }

        CPA_WAIT1();               // V[jt] landed
        __syncthreads();           // P + V visible

        // ---- MMA2: O[m32 x dv64] += P V, k=64 ----
        #pragma unroll
        for (int ks = 0; ks < 8; ++ks) {
            const int c2 = 2 * ks;
            uint32_t a0[4], a1[4];
            ldsm4(a0, pA0 + (uint32_t)(((c2 + ac) ^ lr) << 4));
            ldsm4(a1, pA1 + (uint32_t)(((c2 + ac) ^ lr) << 4));
            const float* vr  = Vs + (8 * ks + t4) * 128;
            const float* vr4 = vr + 4 * 128;
            #pragma unroll
            for (int nf = 0; nf < 8; ++nf) {
                const int vo = ((vb2 + 2 * nf + gh) ^ xv) * 4 + g3;
                uint32_t b0 = __float_as_uint(vr[vo]);    // raw fp32 -> HW tf32
                uint32_t b1 = __float_as_uint(vr4[vo]);
                mma_tf32(oacc[0][nf], a0, b0, b1);
                mma_tf32(oacc[1][nf], a1, b0, b1);
            }
        }
        __syncthreads();           // all warps done reading V[jt]

        // prefetch V[jt+1]
        if (jt + 1 < nj) {
            const int j1 = j0 + BN;
            #pragma unroll
            for (int i2 = 0; i2 < 16; ++i2) {
                int idx = i2 * NTH + tid;  int r = idx >> 5;  int c = idx & 31;
                int gr = j1 + r;  int ok = (gr < len) ? 16 : 0;
                cpa16(smu + SB_V + (uint32_t)(r * 512 + (c ^ ((r & 3) << 1)) * 16),
                      vb + (size_t)(ok ? gr : 0) * HD + c * 4, ok);
            }
        }
        CPA_COMMIT();
    }

    // ---- store O ----
    #pragma unroll
    for (int mf = 0; mf < 2; ++mf) {
        const int r0 = i0 + mbase + mf * 16 + g;
        const int r1 = r0 + 8;
        float* ob0 = out + (size_t)(off + r0) * HD + h * 128 + vbase + 2 * t4;
        float* ob1 = out + (size_t)(off + r1) * HD + h * 128 + vbase + 2 * t4;
        #pragma unroll
        for (int nf = 0; nf < 8; ++nf) {
            if (r0 < len) {
                float2 v; v.x = oacc[mf][nf][0]; v.y = oacc[mf][nf][1];
                *(float2*)(ob0 + nf * 8) = v;
            }
            if (r1 < len) {
                float2 v; v.x = oacc[mf][nf][2]; v.y = oacc[mf][nf][3];
                *(float2*)(ob1 + nf * 8) = v;
            }
        }
    }
}

extern "C" void kernel_launch(void* const* d_in, const int* in_sizes, int n_in,
                              void* d_out, int out_size)
{
    const float* tq      = (const float*)d_in[0];
    const float* tk      = (const float*)d_in[1];
    const float* tv      = (const float*)d_in[2];
    const int*   offsets = (const int*)  d_in[3];
    const int*   p_msl   = (n_in > 4) ? (const int*)d_in[4] : nullptr;
    const int*   p_ssl   = (n_in > 5) ? (const int*)d_in[5] : nullptr;
    float*       out     = (float*)d_out;

    const int B = in_sizes[3] - 1;
    const int smem_bytes = SMEM_FLOATS * (int)sizeof(float);   // 112 KB

    cudaFuncSetAttribute((const void*)hstu_ldsm_kernel,
                         cudaFuncAttributeMaxDynamicSharedMemorySize, smem_bytes);

    dim3 grid(NTILES, 8, B);
    hstu_ldsm_kernel<<<grid, NTH, smem_bytes>>>(tq, tk, tv, offsets,
                                                p_msl, p_ssl, out);
}